// round 8
// baseline (speedup 1.0000x reference)
#include <cuda_runtime.h>
#include <math.h>

#define B_  2
#define NFC 64
#define Hh  256
#define Ww  256
#define HW  (Hh*Ww)
#define DGC 8
#define CGC 8
#define KK  9
#define OMC 216
#define OM_CIN 66
#define OM_CHUNKO 72
#define C1_CIN 128

// Scratch (static device arrays; no runtime allocation)
__device__ float g_warp[(size_t)B_*NFC*HW];   // 33.5 MB
__device__ float g_fea [(size_t)B_*NFC*HW];   // 33.5 MB
__device__ float g_om  [(size_t)B_*OMC*HW];   // 113 MB

// ---- packed f32x2 helpers (Blackwell full-rate fp32 path) ---------------
__device__ __forceinline__ void ffma2(unsigned long long& acc,
                                      unsigned long long a,
                                      unsigned long long b) {
    asm("fma.rn.f32x2 %0, %1, %2, %0;" : "+l"(acc) : "l"(a), "l"(b));
}
__device__ __forceinline__ unsigned long long bcast2(float v) {
    unsigned long long r;
    asm("mov.b64 %0, {%1, %1};" : "=l"(r) : "f"(v));
    return r;
}
__device__ __forceinline__ unsigned long long pack2(float a, float b) {
    unsigned long long r;
    asm("mov.b64 %0, {%1, %2};" : "=l"(r) : "f"(a), "f"(b));
    return r;
}
__device__ __forceinline__ float2 unpack2(unsigned long long v) {
    float2 f;
    asm("mov.b64 {%0, %1}, %2;" : "=f"(f.x), "=f"(f.y) : "l"(v));
    return f;
}

// ---------------------------------------------------------------------------
// Kernel 1: bilinear flow-warp of nbr -> g_warp   (HBM-bound)
// ---------------------------------------------------------------------------
__global__ __launch_bounds__(256) void warp_kernel(const float* __restrict__ nbr,
                                                   const float* __restrict__ flow) {
    int p = blockIdx.x * 256 + threadIdx.x;
    if (p >= B_*HW) return;
    int b = p / HW, s = p % HW;
    int y = s / Ww, x = s % Ww;

    float fx = flow[((size_t)b*2+0)*HW + s];
    float fy = flow[((size_t)b*2+1)*HW + s];
    float py = (float)y + fy, px = (float)x + fx;
    float y0f = floorf(py), x0f = floorf(px);
    float wy = py - y0f, wx = px - x0f;
    int iy0 = (int)y0f, ix0 = (int)x0f;
    int iy1 = iy0 + 1,  ix1 = ix0 + 1;
    bool vy0 = (unsigned)iy0 < Hh, vy1 = (unsigned)iy1 < Hh;
    bool vx0 = (unsigned)ix0 < Ww, vx1 = (unsigned)ix1 < Ww;
    float w00 = (1.f-wy)*(1.f-wx) * (vy0&&vx0 ? 1.f : 0.f);
    float w01 = (1.f-wy)*wx       * (vy0&&vx1 ? 1.f : 0.f);
    float w10 = wy*(1.f-wx)       * (vy1&&vx0 ? 1.f : 0.f);
    float w11 = wy*wx             * (vy1&&vx1 ? 1.f : 0.f);
    int cy0 = min(max(iy0,0),Hh-1), cy1 = min(max(iy1,0),Hh-1);
    int cx0 = min(max(ix0,0),Ww-1), cx1 = min(max(ix1,0),Ww-1);
    int i00 = cy0*Ww+cx0, i01 = cy0*Ww+cx1, i10 = cy1*Ww+cx0, i11 = cy1*Ww+cx1;

    const float* base = nbr + (size_t)b*NFC*HW;
    float* dst = g_warp + (size_t)b*NFC*HW + s;
    #pragma unroll 4
    for (int c = 0; c < NFC; c++) {
        const float* src = base + (size_t)c*HW;
        dst[(size_t)c*HW] = w00*src[i00] + w01*src[i01] + w10*src[i10] + w11*src[i11];
    }
}

// ---------------------------------------------------------------------------
// Kernel 2: conv1 — register-tiled GEMM. Block = 1 row (256 px) x 64 outs.
// Thread tile: 8 outs x 8 px. Inputs staged in smem per 4-cin chunk.
// ---------------------------------------------------------------------------
__global__ __launch_bounds__(256) void conv1_kernel(const float* __restrict__ ref,
                                                    const float* __restrict__ w,
                                                    const float* __restrict__ bias) {
    __shared__ __align__(16) unsigned long long swd[4*9*64];  // dup weights, 18 KB
    __shared__ __align__(16) float si[4*3*264];               // 12.7 KB
    int tid = threadIdx.x;
    int row = blockIdx.x;
    int b = row / Hh, y = row % Hh;
    int to = tid >> 5;          // 0..7 output group
    int tp = tid & 31;          // 0..31 pixel group
    int oo = to * 8;
    int xb = tp * 8;

    unsigned long long acc[8][4];
    #pragma unroll
    for (int o = 0; o < 8; o++)
        #pragma unroll
        for (int pp = 0; pp < 4; pp++) acc[o][pp] = 0ULL;

    #pragma unroll 1
    for (int c0 = 0; c0 < C1_CIN; c0 += 4) {
        __syncthreads();
        // stage duplicated weights [cc][tap][o]
        for (int idx = tid; idx < 4*9*64; idx += 256) {
            int cc = idx / (9*64); int rem = idx % (9*64);
            int tap = rem / 64;   int o = rem % 64;
            float v = w[((size_t)o*C1_CIN + (c0+cc))*9 + tap];
            swd[idx] = bcast2(v);
        }
        // stage input rows [cc][r][col], col 0 = x=-1 pad, col 257 = x=256 pad
        for (int idx = tid; idx < 4*3*264; idx += 256) {
            int cc = idx / 792; int rem = idx % 792;
            int r = rem / 264;  int col = rem % 264;
            int c = c0 + cc;
            int yy = y + r - 1;
            float v = 0.f;
            if (col >= 1 && col <= 256 && yy >= 0 && yy < Hh) {
                int gx = col - 1;
                const float* sp = (c < NFC) ? (g_warp + ((size_t)b*NFC + c)*HW)
                                            : (ref    + ((size_t)b*NFC + (c-NFC))*HW);
                v = sp[yy*Ww + gx];
            }
            si[idx] = v;
        }
        __syncthreads();

        #pragma unroll
        for (int cc = 0; cc < 4; cc++) {
            float rin[3][10];
            #pragma unroll
            for (int r = 0; r < 3; r++) {
                const float* rp = &si[(cc*3 + r)*264 + xb];
                float4 a = *(const float4*)rp;
                float4 bb = *(const float4*)(rp + 4);
                float2 cpair = *(const float2*)(rp + 8);
                rin[r][0]=a.x; rin[r][1]=a.y; rin[r][2]=a.z; rin[r][3]=a.w;
                rin[r][4]=bb.x; rin[r][5]=bb.y; rin[r][6]=bb.z; rin[r][7]=bb.w;
                rin[r][8]=cpair.x; rin[r][9]=cpair.y;
            }
            #pragma unroll
            for (int ky = 0; ky < 3; ky++) {
                #pragma unroll
                for (int kx = 0; kx < 3; kx++) {
                    int tap = ky*3 + kx;
                    unsigned long long piv[4];
                    #pragma unroll
                    for (int pp = 0; pp < 4; pp++)
                        piv[pp] = pack2(rin[ky][2*pp+kx], rin[ky][2*pp+kx+1]);
                    const ulonglong2* wp = (const ulonglong2*)&swd[(cc*9 + tap)*64 + oo];
                    ulonglong2 w01 = wp[0], w23 = wp[1], w45 = wp[2], w67 = wp[3];
                    unsigned long long w8[8] = {w01.x, w01.y, w23.x, w23.y,
                                                w45.x, w45.y, w67.x, w67.y};
                    #pragma unroll
                    for (int o = 0; o < 8; o++)
                        #pragma unroll
                        for (int pp = 0; pp < 4; pp++)
                            ffma2(acc[o][pp], piv[pp], w8[o]);
                }
            }
        }
    }
    // epilogue: bias + ReLU, float2 stores (adjacent pixels)
    #pragma unroll
    for (int o = 0; o < 8; o++) {
        float bo = bias[oo + o];
        float* dst = g_fea + ((size_t)b*NFC + oo + o)*HW + y*Ww + xb;
        #pragma unroll
        for (int pp = 0; pp < 4; pp++) {
            float2 v = unpack2(acc[o][pp]);
            v.x += bo; v.y += bo;
            v.x = v.x > 0.f ? v.x : 0.f;
            v.y = v.y > 0.f ? v.y : 0.f;
            *(float2*)(dst + 2*pp) = v;
        }
    }
}

// ---------------------------------------------------------------------------
// Kernel 3: om conv — register-tiled GEMM. Block = 1 row x 72 outs (grid.y=3).
// Thread tile: 9 outs x 8 px. cin padded to 68 (chunks of 4, zero-filled).
// ---------------------------------------------------------------------------
__global__ __launch_bounds__(256) void om_kernel(const float* __restrict__ flow,
                                                 const float* __restrict__ w,
                                                 const float* __restrict__ bias) {
    __shared__ __align__(16) unsigned long long swd[4*9*80];  // padded groups, 23 KB
    __shared__ __align__(16) float si[4*3*264];               // 12.7 KB
    int tid = threadIdx.x;
    int row = blockIdx.x;
    int ob = blockIdx.y * OM_CHUNKO;
    int b = row / Hh, y = row % Hh;
    int to = tid >> 5;          // 0..7 -> 9-out group
    int tp = tid & 31;
    int oo = to * 9;            // local out base (0..63, 9 wide)
    int xb = tp * 8;

    unsigned long long acc[9][4];
    #pragma unroll
    for (int o = 0; o < 9; o++)
        #pragma unroll
        for (int pp = 0; pp < 4; pp++) acc[o][pp] = 0ULL;

    #pragma unroll 1
    for (int c0 = 0; c0 < OM_CIN; c0 += 4) {   // 17 chunks, last zero-padded
        __syncthreads();
        // stage duplicated weights: [cc][tap][grp*10 + k], k<9 valid
        for (int idx = tid; idx < 4*9*80; idx += 256) {
            int cc = idx / 720; int rem = idx % 720;
            int tap = rem / 80; int slot = rem % 80;
            int grp = slot / 10, k = slot % 10;
            int c = c0 + cc;
            float v = 0.f;
            if (k < 9 && c < OM_CIN) {
                int o = ob + grp*9 + k;
                v = w[((size_t)o*OM_CIN + c)*9 + tap];
            }
            swd[idx] = bcast2(v);
        }
        // stage input rows
        for (int idx = tid; idx < 4*3*264; idx += 256) {
            int cc = idx / 792; int rem = idx % 792;
            int r = rem / 264;  int col = rem % 264;
            int c = c0 + cc;
            int yy = y + r - 1;
            float v = 0.f;
            if (c < OM_CIN && col >= 1 && col <= 256 && yy >= 0 && yy < Hh) {
                int gx = col - 1;
                const float* sp = (c < NFC) ? (g_fea + ((size_t)b*NFC + c)*HW)
                                            : (flow  + ((size_t)b*2 + (c-NFC))*HW);
                v = sp[yy*Ww + gx];
            }
            si[idx] = v;
        }
        __syncthreads();

        #pragma unroll
        for (int cc = 0; cc < 4; cc++) {
            float rin[3][10];
            #pragma unroll
            for (int r = 0; r < 3; r++) {
                const float* rp = &si[(cc*3 + r)*264 + xb];
                float4 a = *(const float4*)rp;
                float4 bb = *(const float4*)(rp + 4);
                float2 cpair = *(const float2*)(rp + 8);
                rin[r][0]=a.x; rin[r][1]=a.y; rin[r][2]=a.z; rin[r][3]=a.w;
                rin[r][4]=bb.x; rin[r][5]=bb.y; rin[r][6]=bb.z; rin[r][7]=bb.w;
                rin[r][8]=cpair.x; rin[r][9]=cpair.y;
            }
            #pragma unroll
            for (int ky = 0; ky < 3; ky++) {
                #pragma unroll
                for (int kx = 0; kx < 3; kx++) {
                    int tap = ky*3 + kx;
                    unsigned long long piv[4];
                    #pragma unroll
                    for (int pp = 0; pp < 4; pp++)
                        piv[pp] = pack2(rin[ky][2*pp+kx], rin[ky][2*pp+kx+1]);
                    const unsigned long long* wb = &swd[(cc*9 + tap)*80 + to*10];
                    const ulonglong2* wp = (const ulonglong2*)wb;
                    ulonglong2 w01 = wp[0], w23 = wp[1], w45 = wp[2], w67 = wp[3];
                    unsigned long long w9[9] = {w01.x, w01.y, w23.x, w23.y,
                                                w45.x, w45.y, w67.x, w67.y, wb[8]};
                    #pragma unroll
                    for (int o = 0; o < 9; o++)
                        #pragma unroll
                        for (int pp = 0; pp < 4; pp++)
                            ffma2(acc[o][pp], piv[pp], w9[o]);
                }
            }
        }
    }
    // epilogue
    #pragma unroll
    for (int o = 0; o < 9; o++) {
        int og = ob + oo + o;
        float bo = bias[og];
        float* dst = g_om + ((size_t)b*OMC + og)*HW + y*Ww + xb;
        #pragma unroll
        for (int pp = 0; pp < 4; pp++) {
            float2 v = unpack2(acc[o][pp]);
            v.x += bo; v.y += bo;
            *(float2*)(dst + 2*pp) = v;
        }
    }
}

// ---------------------------------------------------------------------------
// Kernel 4: fused DCN. 128 thr/block, 2 px/thread (1 row). (Round-6 version)
// ---------------------------------------------------------------------------
__global__ __launch_bounds__(128) void dcn_kernel(const float* __restrict__ nbr,
                                                  const float* __restrict__ flow,
                                                  const float* __restrict__ w,
                                                  const float* __restrict__ bias,
                                                  float* __restrict__ out) {
    __shared__ __align__(16) float sw[KK][CGC][NFC];  // 18 KB
    int tid = threadIdx.x;
    int row = blockIdx.x;
    int b = row / Hh, y = row % Hh;
    int xA = tid, xB = tid + 128;
    int sA = y*Ww + xA, sB = sA + 128;

    float fxA = flow[((size_t)b*2+0)*HW + sA];
    float fyA = flow[((size_t)b*2+1)*HW + sA];
    float fxB = flow[((size_t)b*2+0)*HW + sB];
    float fyB = flow[((size_t)b*2+1)*HW + sB];

    unsigned long long accA[NFC/2], accB[NFC/2];
    #pragma unroll
    for (int j = 0; j < NFC/2; j++) { accA[j] = 0ULL; accB[j] = 0ULL; }

    const float* ombA = g_om + (size_t)b*OMC*HW + sA;
    const float* ombB = g_om + (size_t)b*OMC*HW + sB;

    #pragma unroll 1
    for (int g = 0; g < DGC; g++) {
        __syncthreads();
        for (int i = tid; i < KK*CGC*NFC; i += 128) {
            int k = i / (CGC*NFC); int r = i % (CGC*NFC);
            int cg = r / NFC;      int o = r % NFC;
            sw[k][cg][o] = w[((size_t)o*NFC + (g*CGC+cg))*9 + k];
        }
        __syncthreads();

        const float* base = nbr + ((size_t)b*NFC + g*CGC)*HW;
        #pragma unroll 1
        for (int k = 0; k < KK; k++) {
            int ky = k / 3, kx = k % 3;
            float dyA = ombA[(size_t)(18*g + 2*k    )*HW];
            float dxA = ombA[(size_t)(18*g + 2*k + 1)*HW];
            float mvA = ombA[(size_t)(144 + 9*g + k )*HW];
            float dyB = ombB[(size_t)(18*g + 2*k    )*HW];
            float dxB = ombB[(size_t)(18*g + 2*k + 1)*HW];
            float mvB = ombB[(size_t)(144 + 9*g + k )*HW];
            float mA = 1.f / (1.f + expf(-mvA));
            float mB = 1.f / (1.f + expf(-mvB));

            float spyA = (float)(y - 1 + ky) + dyA + fyA;
            float spxA = (float)(xA - 1 + kx) + dxA + fxA;
            float spyB = (float)(y - 1 + ky) + dyB + fyB;
            float spxB = (float)(xB - 1 + kx) + dxB + fxB;

            float y0fA = floorf(spyA), x0fA = floorf(spxA);
            float wyA = spyA - y0fA, wxA = spxA - x0fA;
            int iy0A = (int)y0fA, ix0A = (int)x0fA;
            int iy1A = iy0A + 1,  ix1A = ix0A + 1;
            bool vy0A = (unsigned)iy0A < Hh, vy1A = (unsigned)iy1A < Hh;
            bool vx0A = (unsigned)ix0A < Ww, vx1A = (unsigned)ix1A < Ww;
            float w00A = mA*(1.f-wyA)*(1.f-wxA) * (vy0A&&vx0A ? 1.f : 0.f);
            float w01A = mA*(1.f-wyA)*wxA       * (vy0A&&vx1A ? 1.f : 0.f);
            float w10A = mA*wyA*(1.f-wxA)       * (vy1A&&vx0A ? 1.f : 0.f);
            float w11A = mA*wyA*wxA             * (vy1A&&vx1A ? 1.f : 0.f);
            int cy0A = min(max(iy0A,0),Hh-1), cy1A = min(max(iy1A,0),Hh-1);
            int cx0A = min(max(ix0A,0),Ww-1), cx1A = min(max(ix1A,0),Ww-1);
            int i00A = cy0A*Ww+cx0A, i01A = cy0A*Ww+cx1A;
            int i10A = cy1A*Ww+cx0A, i11A = cy1A*Ww+cx1A;

            float y0fB = floorf(spyB), x0fB = floorf(spxB);
            float wyB = spyB - y0fB, wxB = spxB - x0fB;
            int iy0B = (int)y0fB, ix0B = (int)x0fB;
            int iy1B = iy0B + 1,  ix1B = ix0B + 1;
            bool vy0B = (unsigned)iy0B < Hh, vy1B = (unsigned)iy1B < Hh;
            bool vx0B = (unsigned)ix0B < Ww, vx1B = (unsigned)ix1B < Ww;
            float w00B = mB*(1.f-wyB)*(1.f-wxB) * (vy0B&&vx0B ? 1.f : 0.f);
            float w01B = mB*(1.f-wyB)*wxB       * (vy0B&&vx1B ? 1.f : 0.f);
            float w10B = mB*wyB*(1.f-wxB)       * (vy1B&&vx0B ? 1.f : 0.f);
            float w11B = mB*wyB*wxB             * (vy1B&&vx1B ? 1.f : 0.f);
            int cy0B = min(max(iy0B,0),Hh-1), cy1B = min(max(iy1B,0),Hh-1);
            int cx0B = min(max(ix0B,0),Ww-1), cx1B = min(max(ix1B,0),Ww-1);
            int i00B = cy0B*Ww+cx0B, i01B = cy0B*Ww+cx1B;
            int i10B = cy1B*Ww+cx0B, i11B = cy1B*Ww+cx1B;

            float vA[CGC], vB[CGC];
            #pragma unroll
            for (int cg = 0; cg < CGC; cg++) {
                const float* src = base + (size_t)cg*HW;
                vA[cg] = w00A*src[i00A] + w01A*src[i01A] + w10A*src[i10A] + w11A*src[i11A];
                vB[cg] = w00B*src[i00B] + w01B*src[i01B] + w10B*src[i10B] + w11B*src[i11B];
            }
            #pragma unroll
            for (int cg = 0; cg < CGC; cg++) {
                unsigned long long ivA = bcast2(vA[cg]);
                unsigned long long ivB = bcast2(vB[cg]);
                const ulonglong2* swp = (const ulonglong2*)&sw[k][cg][0];
                #pragma unroll
                for (int j = 0; j < NFC/4; j++) {
                    ulonglong2 wv = swp[j];
                    ffma2(accA[2*j+0], ivA, wv.x);
                    ffma2(accA[2*j+1], ivA, wv.y);
                    ffma2(accB[2*j+0], ivB, wv.x);
                    ffma2(accB[2*j+1], ivB, wv.y);
                }
            }
        }
    }
    float* dstA = out + (size_t)b*NFC*HW + sA;
    float* dstB = out + (size_t)b*NFC*HW + sB;
    #pragma unroll
    for (int j = 0; j < NFC/2; j++) {
        float2 vA = unpack2(accA[j]);
        float2 vB = unpack2(accB[j]);
        float b0 = bias[2*j+0], b1 = bias[2*j+1];
        dstA[(size_t)(2*j+0)*HW] = vA.x + b0;
        dstA[(size_t)(2*j+1)*HW] = vA.y + b1;
        dstB[(size_t)(2*j+0)*HW] = vB.x + b0;
        dstB[(size_t)(2*j+1)*HW] = vB.y + b1;
    }
}

// ---------------------------------------------------------------------------
extern "C" void kernel_launch(void* const* d_in, const int* in_sizes, int n_in,
                              void* d_out, int out_size) {
    const float* nbr  = (const float*)d_in[0];
    const float* ref  = (const float*)d_in[1];
    const float* flow = (const float*)d_in[2];
    const float* c1w  = (const float*)d_in[3];
    const float* c1b  = (const float*)d_in[4];
    const float* omw  = (const float*)d_in[5];
    const float* ombi = (const float*)d_in[6];
    const float* dw   = (const float*)d_in[7];
    const float* db   = (const float*)d_in[8];
    float* out = (float*)d_out;

    int nrows = B_ * Hh;                 // 512 row-blocks
    warp_kernel <<<(B_*HW)/256, 256>>>(nbr, flow);
    conv1_kernel<<<nrows, 256>>>(ref, c1w, c1b);
    om_kernel   <<<dim3(nrows, OMC/OM_CHUNKO), 256>>>(flow, omw, ombi);
    dcn_kernel  <<<nrows, 128>>>(nbr, flow, dw, db, out);
}

// round 9
// speedup vs baseline: 1.3774x; 1.3774x over previous
#include <cuda_runtime.h>
#include <math.h>

#define B_  2
#define NFC 64
#define Hh  256
#define Ww  256
#define HW  (Hh*Ww)
#define DGC 8
#define CGC 8
#define KK  9
#define OMC 216
#define OM_CIN 66
#define OM_CHUNK 36
#define C1_CIN 128

// Scratch (static device arrays; no runtime allocation)
__device__ float g_warp[(size_t)B_*NFC*HW];   // 33.5 MB
__device__ float g_fea [(size_t)B_*NFC*HW];   // 33.5 MB
__device__ float g_om  [(size_t)B_*OMC*HW];   // 113 MB
__device__ float g_nbrT[(size_t)B_*NFC*HW];   // 33.5 MB, [b][g][s][cg]

// ---- packed f32x2 helpers ----------------------------------------------
__device__ __forceinline__ void ffma2(unsigned long long& acc,
                                      unsigned long long a,
                                      unsigned long long b) {
    asm("fma.rn.f32x2 %0, %1, %2, %0;" : "+l"(acc) : "l"(a), "l"(b));
}
__device__ __forceinline__ unsigned long long bcast2(float v) {
    unsigned long long r;
    asm("mov.b64 %0, {%1, %1};" : "=l"(r) : "f"(v));
    return r;
}
__device__ __forceinline__ float2 unpack2(unsigned long long v) {
    float2 f;
    asm("mov.b64 {%0, %1}, %2;" : "=f"(f.x), "=f"(f.y) : "l"(v));
    return f;
}

// ---------------------------------------------------------------------------
// Kernel 1: bilinear flow-warp of nbr -> g_warp   (HBM-bound)
// ---------------------------------------------------------------------------
__global__ __launch_bounds__(256) void warp_kernel(const float* __restrict__ nbr,
                                                   const float* __restrict__ flow) {
    int p = blockIdx.x * 256 + threadIdx.x;
    if (p >= B_*HW) return;
    int b = p / HW, s = p % HW;
    int y = s / Ww, x = s % Ww;

    float fx = flow[((size_t)b*2+0)*HW + s];
    float fy = flow[((size_t)b*2+1)*HW + s];
    float py = (float)y + fy, px = (float)x + fx;
    float y0f = floorf(py), x0f = floorf(px);
    float wy = py - y0f, wx = px - x0f;
    int iy0 = (int)y0f, ix0 = (int)x0f;
    int iy1 = iy0 + 1,  ix1 = ix0 + 1;
    bool vy0 = (unsigned)iy0 < Hh, vy1 = (unsigned)iy1 < Hh;
    bool vx0 = (unsigned)ix0 < Ww, vx1 = (unsigned)ix1 < Ww;
    float w00 = (1.f-wy)*(1.f-wx) * (vy0&&vx0 ? 1.f : 0.f);
    float w01 = (1.f-wy)*wx       * (vy0&&vx1 ? 1.f : 0.f);
    float w10 = wy*(1.f-wx)       * (vy1&&vx0 ? 1.f : 0.f);
    float w11 = wy*wx             * (vy1&&vx1 ? 1.f : 0.f);
    int cy0 = min(max(iy0,0),Hh-1), cy1 = min(max(iy1,0),Hh-1);
    int cx0 = min(max(ix0,0),Ww-1), cx1 = min(max(ix1,0),Ww-1);
    int i00 = cy0*Ww+cx0, i01 = cy0*Ww+cx1, i10 = cy1*Ww+cx0, i11 = cy1*Ww+cx1;

    const float* base = nbr + (size_t)b*NFC*HW;
    float* dst = g_warp + (size_t)b*NFC*HW + s;
    #pragma unroll 4
    for (int c = 0; c < NFC; c++) {
        const float* src = base + (size_t)c*HW;
        dst[(size_t)c*HW] = w00*src[i00] + w01*src[i01] + w10*src[i10] + w11*src[i11];
    }
}

// ---------------------------------------------------------------------------
// Kernel 1b: transpose nbr [b][c][s] -> g_nbrT [b][g][s][cg]  (group-chan-last)
// ---------------------------------------------------------------------------
__global__ __launch_bounds__(256) void transpose_kernel(const float* __restrict__ nbr) {
    int p = blockIdx.x * 256 + threadIdx.x;   // (b,g,s)
    int s = p % HW;
    int bg = p / HW;
    int g = bg % DGC, b = bg / DGC;

    const float* src = nbr + ((size_t)b*NFC + g*CGC)*HW + s;
    float v[CGC];
    #pragma unroll
    for (int cg = 0; cg < CGC; cg++) v[cg] = src[(size_t)cg*HW];

    float* dst = g_nbrT + (((size_t)bg)*HW + s)*CGC;
    float4 lo = make_float4(v[0], v[1], v[2], v[3]);
    float4 hi = make_float4(v[4], v[5], v[6], v[7]);
    *(float4*)dst = lo;
    *(float4*)(dst + 4) = hi;
}

// ---------------------------------------------------------------------------
// Kernel 2: conv1 3x3, cin=128 -> 64, ReLU.  128 thr/block, 2 px/thread (R6)
// ---------------------------------------------------------------------------
__global__ __launch_bounds__(128) void conv1_kernel(const float* __restrict__ ref,
                                                    const float* __restrict__ w,
                                                    const float* __restrict__ bias) {
    __shared__ __align__(16) float sw[8][9][NFC];   // 18 KB
    int tid = threadIdx.x;
    int row = blockIdx.x;
    int b = row / Hh, y = row % Hh;
    int xA = tid, xB = tid + 128;
    int sA = y*Ww + xA, sB = sA + 128;

    unsigned long long accA[NFC/2], accB[NFC/2];
    #pragma unroll
    for (int j = 0; j < NFC/2; j++) { accA[j] = 0ULL; accB[j] = 0ULL; }

    #pragma unroll 1
    for (int c0 = 0; c0 < C1_CIN; c0 += 8) {
        __syncthreads();
        for (int i = tid; i < 8*9*NFC; i += 128) {
            int cc = i / (9*NFC); int r = i % (9*NFC);
            int tap = r / NFC;    int o = r % NFC;
            sw[cc][tap][o] = w[((size_t)o*C1_CIN + (c0+cc))*9 + tap];
        }
        __syncthreads();
        #pragma unroll 1
        for (int cc = 0; cc < 8; cc++) {
            int c = c0 + cc;
            const float* src = (c < NFC) ? (g_warp + ((size_t)b*NFC + c)*HW)
                                         : (ref    + ((size_t)b*NFC + (c-NFC))*HW);
            float tA[9], tB[9];
            #pragma unroll
            for (int ky = 0; ky < 3; ky++) {
                int yy = y + ky - 1;
                bool vy = (unsigned)yy < Hh;
                const float* srow = src + yy*Ww;
                #pragma unroll
                for (int kx = 0; kx < 3; kx++) {
                    int x1 = xA + kx - 1, x2 = xB + kx - 1;
                    tA[ky*3+kx] = (vy && (unsigned)x1 < Ww) ? srow[x1] : 0.f;
                    tB[ky*3+kx] = (vy && (unsigned)x2 < Ww) ? srow[x2] : 0.f;
                }
            }
            #pragma unroll
            for (int tap = 0; tap < 9; tap++) {
                unsigned long long ivA = bcast2(tA[tap]);
                unsigned long long ivB = bcast2(tB[tap]);
                const ulonglong2* swp = (const ulonglong2*)&sw[cc][tap][0];
                #pragma unroll
                for (int j = 0; j < NFC/4; j++) {
                    ulonglong2 wv = swp[j];
                    ffma2(accA[2*j+0], ivA, wv.x);
                    ffma2(accA[2*j+1], ivA, wv.y);
                    ffma2(accB[2*j+0], ivB, wv.x);
                    ffma2(accB[2*j+1], ivB, wv.y);
                }
            }
        }
    }
    float* dstA = g_fea + (size_t)b*NFC*HW + sA;
    float* dstB = g_fea + (size_t)b*NFC*HW + sB;
    #pragma unroll
    for (int j = 0; j < NFC/2; j++) {
        float2 vA = unpack2(accA[j]);
        float2 vB = unpack2(accB[j]);
        float b0 = bias[2*j+0], b1 = bias[2*j+1];
        float a0 = vA.x + b0, a1 = vA.y + b1;
        float c0v = vB.x + b0, c1v = vB.y + b1;
        dstA[(size_t)(2*j+0)*HW] = a0 > 0.f ? a0 : 0.f;
        dstA[(size_t)(2*j+1)*HW] = a1 > 0.f ? a1 : 0.f;
        dstB[(size_t)(2*j+0)*HW] = c0v > 0.f ? c0v : 0.f;
        dstB[(size_t)(2*j+1)*HW] = c1v > 0.f ? c1v : 0.f;
    }
}

// ---------------------------------------------------------------------------
// Kernel 3: om conv 3x3, cin=66 -> 216. 128 thr, 2 px/thread, 36 outs/z (R6)
// ---------------------------------------------------------------------------
__global__ __launch_bounds__(128) void om_kernel(const float* __restrict__ flow,
                                                 const float* __restrict__ w,
                                                 const float* __restrict__ bias) {
    __shared__ __align__(16) float sw[8][9][OM_CHUNK];  // 10.4 KB
    int tid = threadIdx.x;
    int row = blockIdx.x;
    int ob = blockIdx.y * OM_CHUNK;
    int b = row / Hh, y = row % Hh;
    int xA = tid, xB = tid + 128;
    int sA = y*Ww + xA, sB = sA + 128;

    unsigned long long accA[OM_CHUNK/2], accB[OM_CHUNK/2];
    #pragma unroll
    for (int j = 0; j < OM_CHUNK/2; j++) { accA[j] = 0ULL; accB[j] = 0ULL; }

    #pragma unroll 1
    for (int c0 = 0; c0 < OM_CIN; c0 += 8) {
        int nc = min(8, OM_CIN - c0);
        __syncthreads();
        for (int i = tid; i < nc*9*OM_CHUNK; i += 128) {
            int cc = i / (9*OM_CHUNK); int r = i % (9*OM_CHUNK);
            int tap = r / OM_CHUNK;    int o = r % OM_CHUNK;
            sw[cc][tap][o] = w[((size_t)(ob+o)*OM_CIN + (c0+cc))*9 + tap];
        }
        __syncthreads();
        #pragma unroll 1
        for (int cc = 0; cc < nc; cc++) {
            int c = c0 + cc;
            const float* src = (c < NFC) ? (g_fea + ((size_t)b*NFC + c)*HW)
                                         : (flow  + ((size_t)b*2 + (c-NFC))*HW);
            float tA[9], tB[9];
            #pragma unroll
            for (int ky = 0; ky < 3; ky++) {
                int yy = y + ky - 1;
                bool vy = (unsigned)yy < Hh;
                const float* srow = src + yy*Ww;
                #pragma unroll
                for (int kx = 0; kx < 3; kx++) {
                    int x1 = xA + kx - 1, x2 = xB + kx - 1;
                    tA[ky*3+kx] = (vy && (unsigned)x1 < Ww) ? srow[x1] : 0.f;
                    tB[ky*3+kx] = (vy && (unsigned)x2 < Ww) ? srow[x2] : 0.f;
                }
            }
            #pragma unroll
            for (int tap = 0; tap < 9; tap++) {
                unsigned long long ivA = bcast2(tA[tap]);
                unsigned long long ivB = bcast2(tB[tap]);
                const ulonglong2* swp = (const ulonglong2*)&sw[cc][tap][0];
                #pragma unroll
                for (int j = 0; j < OM_CHUNK/4; j++) {
                    ulonglong2 wv = swp[j];
                    ffma2(accA[2*j+0], ivA, wv.x);
                    ffma2(accA[2*j+1], ivA, wv.y);
                    ffma2(accB[2*j+0], ivB, wv.x);
                    ffma2(accB[2*j+1], ivB, wv.y);
                }
            }
        }
    }
    float* dstA = g_om + (size_t)b*OMC*HW + (size_t)ob*HW + sA;
    float* dstB = g_om + (size_t)b*OMC*HW + (size_t)ob*HW + sB;
    #pragma unroll
    for (int j = 0; j < OM_CHUNK/2; j++) {
        float2 vA = unpack2(accA[j]);
        float2 vB = unpack2(accB[j]);
        float b0 = bias[ob+2*j+0], b1 = bias[ob+2*j+1];
        dstA[(size_t)(2*j+0)*HW] = vA.x + b0;
        dstA[(size_t)(2*j+1)*HW] = vA.y + b1;
        dstB[(size_t)(2*j+0)*HW] = vB.x + b0;
        dstB[(size_t)(2*j+1)*HW] = vB.y + b1;
    }
}

// ---------------------------------------------------------------------------
// Kernel 4: fused DCN with vectorized gathers from g_nbrT.
// ---------------------------------------------------------------------------
__device__ __forceinline__ void gather8(const float* __restrict__ baseT,
                                        int i00, int i01, int i10, int i11,
                                        float w00, float w01, float w10, float w11,
                                        float* v) {
    const float* p00 = baseT + (size_t)i00*CGC;
    const float* p01 = baseT + (size_t)i01*CGC;
    const float* p10 = baseT + (size_t)i10*CGC;
    const float* p11 = baseT + (size_t)i11*CGC;
    float4 a0 = *(const float4*)p00, a1 = *(const float4*)(p00+4);
    float4 b0 = *(const float4*)p01, b1 = *(const float4*)(p01+4);
    float4 c0 = *(const float4*)p10, c1 = *(const float4*)(p10+4);
    float4 d0 = *(const float4*)p11, d1 = *(const float4*)(p11+4);
    v[0] = w00*a0.x + w01*b0.x + w10*c0.x + w11*d0.x;
    v[1] = w00*a0.y + w01*b0.y + w10*c0.y + w11*d0.y;
    v[2] = w00*a0.z + w01*b0.z + w10*c0.z + w11*d0.z;
    v[3] = w00*a0.w + w01*b0.w + w10*c0.w + w11*d0.w;
    v[4] = w00*a1.x + w01*b1.x + w10*c1.x + w11*d1.x;
    v[5] = w00*a1.y + w01*b1.y + w10*c1.y + w11*d1.y;
    v[6] = w00*a1.z + w01*b1.z + w10*c1.z + w11*d1.z;
    v[7] = w00*a1.w + w01*b1.w + w10*c1.w + w11*d1.w;
}

__global__ __launch_bounds__(128) void dcn_kernel(const float* __restrict__ flow,
                                                  const float* __restrict__ w,
                                                  const float* __restrict__ bias,
                                                  float* __restrict__ out) {
    __shared__ __align__(16) float sw[KK][CGC][NFC];  // 18 KB
    int tid = threadIdx.x;
    int row = blockIdx.x;
    int b = row / Hh, y = row % Hh;
    int xA = tid, xB = tid + 128;
    int sA = y*Ww + xA, sB = sA + 128;

    float fxA = flow[((size_t)b*2+0)*HW + sA];
    float fyA = flow[((size_t)b*2+1)*HW + sA];
    float fxB = flow[((size_t)b*2+0)*HW + sB];
    float fyB = flow[((size_t)b*2+1)*HW + sB];

    unsigned long long accA[NFC/2], accB[NFC/2];
    #pragma unroll
    for (int j = 0; j < NFC/2; j++) { accA[j] = 0ULL; accB[j] = 0ULL; }

    const float* ombA = g_om + (size_t)b*OMC*HW + sA;
    const float* ombB = g_om + (size_t)b*OMC*HW + sB;

    #pragma unroll 1
    for (int g = 0; g < DGC; g++) {
        __syncthreads();
        for (int i = tid; i < KK*CGC*NFC; i += 128) {
            int k = i / (CGC*NFC); int r = i % (CGC*NFC);
            int cg = r / NFC;      int o = r % NFC;
            sw[k][cg][o] = w[((size_t)o*NFC + (g*CGC+cg))*9 + k];
        }
        __syncthreads();

        const float* baseT = g_nbrT + ((size_t)(b*DGC + g))*HW*CGC;
        #pragma unroll 1
        for (int k = 0; k < KK; k++) {
            int ky = k / 3, kx = k % 3;
            float dyA = ombA[(size_t)(18*g + 2*k    )*HW];
            float dxA = ombA[(size_t)(18*g + 2*k + 1)*HW];
            float mvA = ombA[(size_t)(144 + 9*g + k )*HW];
            float dyB = ombB[(size_t)(18*g + 2*k    )*HW];
            float dxB = ombB[(size_t)(18*g + 2*k + 1)*HW];
            float mvB = ombB[(size_t)(144 + 9*g + k )*HW];
            float mA = 1.f / (1.f + expf(-mvA));
            float mB = 1.f / (1.f + expf(-mvB));

            float spyA = (float)(y - 1 + ky) + dyA + fyA;
            float spxA = (float)(xA - 1 + kx) + dxA + fxA;
            float spyB = (float)(y - 1 + ky) + dyB + fyB;
            float spxB = (float)(xB - 1 + kx) + dxB + fxB;

            float y0fA = floorf(spyA), x0fA = floorf(spxA);
            float wyA = spyA - y0fA, wxA = spxA - x0fA;
            int iy0A = (int)y0fA, ix0A = (int)x0fA;
            int iy1A = iy0A + 1,  ix1A = ix0A + 1;
            bool vy0A = (unsigned)iy0A < Hh, vy1A = (unsigned)iy1A < Hh;
            bool vx0A = (unsigned)ix0A < Ww, vx1A = (unsigned)ix1A < Ww;
            float w00A = mA*(1.f-wyA)*(1.f-wxA) * (vy0A&&vx0A ? 1.f : 0.f);
            float w01A = mA*(1.f-wyA)*wxA       * (vy0A&&vx1A ? 1.f : 0.f);
            float w10A = mA*wyA*(1.f-wxA)       * (vy1A&&vx0A ? 1.f : 0.f);
            float w11A = mA*wyA*wxA             * (vy1A&&vx1A ? 1.f : 0.f);
            int cy0A = min(max(iy0A,0),Hh-1), cy1A = min(max(iy1A,0),Hh-1);
            int cx0A = min(max(ix0A,0),Ww-1), cx1A = min(max(ix1A,0),Ww-1);

            float y0fB = floorf(spyB), x0fB = floorf(spxB);
            float wyB = spyB - y0fB, wxB = spxB - x0fB;
            int iy0B = (int)y0fB, ix0B = (int)x0fB;
            int iy1B = iy0B + 1,  ix1B = ix0B + 1;
            bool vy0B = (unsigned)iy0B < Hh, vy1B = (unsigned)iy1B < Hh;
            bool vx0B = (unsigned)ix0B < Ww, vx1B = (unsigned)ix1B < Ww;
            float w00B = mB*(1.f-wyB)*(1.f-wxB) * (vy0B&&vx0B ? 1.f : 0.f);
            float w01B = mB*(1.f-wyB)*wxB       * (vy0B&&vx1B ? 1.f : 0.f);
            float w10B = mB*wyB*(1.f-wxB)       * (vy1B&&vx0B ? 1.f : 0.f);
            float w11B = mB*wyB*wxB             * (vy1B&&vx1B ? 1.f : 0.f);
            int cy0B = min(max(iy0B,0),Hh-1), cy1B = min(max(iy1B,0),Hh-1);
            int cx0B = min(max(ix0B,0),Ww-1), cx1B = min(max(ix1B,0),Ww-1);

            float vA[CGC], vB[CGC];
            gather8(baseT, cy0A*Ww+cx0A, cy0A*Ww+cx1A, cy1A*Ww+cx0A, cy1A*Ww+cx1A,
                    w00A, w01A, w10A, w11A, vA);
            gather8(baseT, cy0B*Ww+cx0B, cy0B*Ww+cx1B, cy1B*Ww+cx0B, cy1B*Ww+cx1B,
                    w00B, w01B, w10B, w11B, vB);

            #pragma unroll
            for (int cg = 0; cg < CGC; cg++) {
                unsigned long long ivA = bcast2(vA[cg]);
                unsigned long long ivB = bcast2(vB[cg]);
                const ulonglong2* swp = (const ulonglong2*)&sw[k][cg][0];
                #pragma unroll
                for (int j = 0; j < NFC/4; j++) {
                    ulonglong2 wv = swp[j];
                    ffma2(accA[2*j+0], ivA, wv.x);
                    ffma2(accA[2*j+1], ivA, wv.y);
                    ffma2(accB[2*j+0], ivB, wv.x);
                    ffma2(accB[2*j+1], ivB, wv.y);
                }
            }
        }
    }
    float* dstA = out + (size_t)b*NFC*HW + sA;
    float* dstB = out + (size_t)b*NFC*HW + sB;
    #pragma unroll
    for (int j = 0; j < NFC/2; j++) {
        float2 vA = unpack2(accA[j]);
        float2 vB = unpack2(accB[j]);
        float b0 = bias[2*j+0], b1 = bias[2*j+1];
        dstA[(size_t)(2*j+0)*HW] = vA.x + b0;
        dstA[(size_t)(2*j+1)*HW] = vA.y + b1;
        dstB[(size_t)(2*j+0)*HW] = vB.x + b0;
        dstB[(size_t)(2*j+1)*HW] = vB.y + b1;
    }
}

// ---------------------------------------------------------------------------
extern "C" void kernel_launch(void* const* d_in, const int* in_sizes, int n_in,
                              void* d_out, int out_size) {
    const float* nbr  = (const float*)d_in[0];
    const float* ref  = (const float*)d_in[1];
    const float* flow = (const float*)d_in[2];
    const float* c1w  = (const float*)d_in[3];
    const float* c1b  = (const float*)d_in[4];
    const float* omw  = (const float*)d_in[5];
    const float* ombi = (const float*)d_in[6];
    const float* dw   = (const float*)d_in[7];
    const float* db   = (const float*)d_in[8];
    float* out = (float*)d_out;

    int nrows = B_ * Hh;                 // 512 row-blocks
    warp_kernel     <<<(B_*HW)/256, 256>>>(nbr, flow);
    transpose_kernel<<<(B_*DGC*HW)/256, 256>>>(nbr);
    conv1_kernel    <<<nrows, 128>>>(ref, c1w, c1b);
    om_kernel       <<<dim3(nrows, OMC/OM_CHUNK), 128>>>(flow, omw, ombi);
    dcn_kernel      <<<nrows, 128>>>(flow, dw, db, out);
}